// round 11
// baseline (speedup 1.0000x reference)
#include <cuda_runtime.h>
#include <cuda_bf16.h>
#include <cstdint>

#define NNODES   100000
#define SSAMP    16
#define NODE_DIM 128
#define EDGE_DIM 64
#define EMB_DIM  128
#define KTOT     320            // 128 self + 128 neigh-agg + 64 edge-mean

// ---------------- device-global scratch (no allocs allowed) ------------------
__device__ __align__(16) __nv_bfloat16 g_Xh[(size_t)NNODES * KTOT];
__device__ __align__(16) __nv_bfloat16 g_Xl[(size_t)NNODES * KTOT];
__device__ __align__(16) __nv_bfloat16 g_Wh[EMB_DIM * KTOT];  // folded W^T [n][k], hi
__device__ __align__(16) __nv_bfloat16 g_Wl[EMB_DIM * KTOT];  // lo
__device__ float g_bias[EMB_DIM];

// ---------------- helpers ----------------------------------------------------
__device__ __forceinline__ uint32_t smem_u32(const void* p) {
    uint32_t a;
    asm("{ .reg .u64 t; cvta.to.shared.u64 t, %1; cvt.u32.u64 %0, t; }" : "=r"(a) : "l"(p));
    return a;
}
__device__ __forceinline__ void ldsm_x4(uint32_t* r, uint32_t addr) {
    asm volatile("ldmatrix.sync.aligned.m8n8.x4.shared.b16 {%0,%1,%2,%3}, [%4];"
        : "=r"(r[0]), "=r"(r[1]), "=r"(r[2]), "=r"(r[3]) : "r"(addr));
}
__device__ __forceinline__ void mma16816(float* d, const uint32_t* a, const uint32_t* b) {
    asm volatile("mma.sync.aligned.m16n8k16.row.col.f32.bf16.bf16.f32 "
        "{%0,%1,%2,%3}, {%4,%5,%6,%7}, {%8,%9}, {%0,%1,%2,%3};"
        : "+f"(d[0]), "+f"(d[1]), "+f"(d[2]), "+f"(d[3])
        : "r"(a[0]), "r"(a[1]), "r"(a[2]), "r"(a[3]), "r"(b[0]), "r"(b[1]));
}
__device__ __forceinline__ void cpa16(uint32_t dst, const void* src) {
    asm volatile("cp.async.cg.shared.global [%0], [%1], 16;" :: "r"(dst), "l"(src));
}
#define CP_COMMIT() asm volatile("cp.async.commit_group;" ::: "memory")
#define CP_WAIT1()  asm volatile("cp.async.wait_group 1;" ::: "memory")
#define CP_WAIT0()  asm volatile("cp.async.wait_group 0;" ::: "memory")

__device__ __forceinline__ uint32_t pack_bf2(float x, float y) {
    __nv_bfloat162 h = __floats2bfloat162_rn(x, y);
    return *(uint32_t*)&h;
}
__device__ __forceinline__ void split_store_g(__nv_bfloat16* hp, __nv_bfloat16* lp, float4 v) {
    __nv_bfloat16 hx = __float2bfloat16_rn(v.x);
    __nv_bfloat16 hy = __float2bfloat16_rn(v.y);
    __nv_bfloat16 hz = __float2bfloat16_rn(v.z);
    __nv_bfloat16 hw = __float2bfloat16_rn(v.w);
    __nv_bfloat162 h01 = __halves2bfloat162(hx, hy);
    __nv_bfloat162 h23 = __halves2bfloat162(hz, hw);
    uint32_t l01 = pack_bf2(v.x - __bfloat162float(hx), v.y - __bfloat162float(hy));
    uint32_t l23 = pack_bf2(v.z - __bfloat162float(hz), v.w - __bfloat162float(hw));
    *(uint2*)hp = make_uint2(*(uint32_t*)&h01, *(uint32_t*)&h23);
    *(uint2*)lp = make_uint2(l01, l23);
}

// ===========================================================================
// K1: everything-per-node kernel (warp/node):
//   - self fp32 row -> split bf16 -> X cols 0:127
//   - fp32 gather-mean of 16 src rows (L2)     -> X cols 128:255
//   - edge mean (DRAM stream)                  -> X cols 256:319
//   Blocks >= AGGB do the weight fold.
// ===========================================================================
#define AGGB  12500
#define FOLDB 41

__global__ __launch_bounds__(256) void aggregate_all(
        const float* __restrict__ node_feat,
        const float* __restrict__ edge_feat,
        const int*   __restrict__ src_idx,
        const float* __restrict__ W_edge, const float* __restrict__ b_edge,
        const float* __restrict__ W_lin,  const float* __restrict__ b_lin) {
    const int tid = threadIdx.x;
    if (blockIdx.x >= AGGB) {
        // ---------------- weight fold ----------------
        int kid = blockIdx.x - AGGB;           // 0..40
        if (kid == 40) {
            int j = tid;
            if (j < EMB_DIM) {
                float acc = b_lin[j];
                for (int c = 0; c < NODE_DIM; c++)
                    acc += b_edge[c] * W_lin[(NODE_DIM + c) * EMB_DIM + j];
                g_bias[j] = acc;
            }
            return;
        }
        int kk = tid >> 7;
        int j  = tid & 127;
        #pragma unroll
        for (int r = 0; r < 4; r++) {
            int k = kid * 8 + r * 2 + kk;      // 0..319
            float w;
            if (k < 2 * NODE_DIM) {
                w = W_lin[k * EMB_DIM + j];
            } else {
                int e = k - 2 * NODE_DIM;
                float acc = 0.f;
                #pragma unroll 4
                for (int c = 0; c < NODE_DIM; c++)
                    acc += W_edge[e * NODE_DIM + c] * W_lin[(NODE_DIM + c) * EMB_DIM + j];
                w = acc;
            }
            __nv_bfloat16 h = __float2bfloat16_rn(w);
            g_Wh[j * KTOT + k] = h;
            g_Wl[j * KTOT + k] = __float2bfloat16_rn(w - __bfloat162float(h));
        }
        return;
    }

    // ---------------- per-node aggregation ----------------
    int node = (int)((blockIdx.x * 256 + tid) >> 5);
    if (node >= NNODES) return;
    int lane = tid & 31;

    // self feature (fp32, issues early)
    float4 sf = *(const float4*)(node_feat + (size_t)node * NODE_DIM + lane * 4);

    // edge mean (lanes split even/odd rows; DRAM stream)
    const float* ep = edge_feat + (size_t)node * (SSAMP * EDGE_DIM);
    int halfrow = lane >> 4, cg = lane & 15;
    float4 ea = make_float4(0.f, 0.f, 0.f, 0.f);
    #pragma unroll
    for (int r = 0; r < SSAMP; r += 2) {
        float4 v = *(const float4*)(ep + (size_t)(r + halfrow) * EDGE_DIM + cg * 4);
        ea.x += v.x; ea.y += v.y; ea.z += v.z; ea.w += v.w;
    }

    // neighbor gather mean (fp32 rows, L2-resident)
    int s = 0;
    if (lane < SSAMP) s = src_idx[(size_t)node * SSAMP + lane];
    float4 na = make_float4(0.f, 0.f, 0.f, 0.f);
    #pragma unroll
    for (int r = 0; r < SSAMP; r++) {
        int sr = __shfl_sync(0xffffffffu, s, r);
        float4 v = *(const float4*)(node_feat + (size_t)sr * NODE_DIM + lane * 4);
        na.x += v.x; na.y += v.y; na.z += v.z; na.w += v.w;
    }

    ea.x += __shfl_xor_sync(0xffffffffu, ea.x, 16);
    ea.y += __shfl_xor_sync(0xffffffffu, ea.y, 16);
    ea.z += __shfl_xor_sync(0xffffffffu, ea.z, 16);
    ea.w += __shfl_xor_sync(0xffffffffu, ea.w, 16);

    const float inv = 1.0f / (float)SSAMP;

    // self -> cols 0:127
    split_store_g(g_Xh + (size_t)node * KTOT + lane * 4,
                  g_Xl + (size_t)node * KTOT + lane * 4, sf);

    // neigh mean -> cols 128:255
    na.x *= inv; na.y *= inv; na.z *= inv; na.w *= inv;
    split_store_g(g_Xh + (size_t)node * KTOT + 128 + lane * 4,
                  g_Xl + (size_t)node * KTOT + 128 + lane * 4, na);

    // edge mean -> cols 256:319
    if (lane < 16) {
        ea.x *= inv; ea.y *= inv; ea.z *= inv; ea.w *= inv;
        split_store_g(g_Xh + (size_t)node * KTOT + 256 + cg * 4,
                      g_Xl + (size_t)node * KTOT + 256 + cg * 4, ea);
    }
}

// ===========================================================================
// K2: split-bf16 GEMM, XOR-swizzled 64B smem rows, 3-stage cp.async ring.
//   (byte-identical to round-8/10 best)
// ===========================================================================
#define ABYTES   8192                     // 128 rows x 64B
#define STAGE    (4 * ABYTES)             // Ah, Al, Bh, Bl = 32KB
#define NSTAGE   3
#define SM_TOTAL (NSTAGE * STAGE)         // 98304

__global__ __launch_bounds__(256, 2) void gemm_mma(float* __restrict__ out) {
    extern __shared__ unsigned char smem[];
    const int tid  = threadIdx.x;
    const int lane = tid & 31;
    const int wid  = tid >> 5;
    const int m0   = blockIdx.x * 128;

    const int mw = (wid & 3) * 32;
    const int nw = (wid >> 2) * 64;
    const uint32_t sb = smem_u32(smem);

    const int ra  = mw + (lane & 15);
    const int ahi = lane >> 4;
    const int swa = (ra >> 1) & 3;
    const uint32_t aRow = (uint32_t)(ra * 64);

    const int rb  = nw + ((lane >> 4) << 3) + (lane & 7);
    const int bhi = (lane >> 3) & 1;
    const int swb = (rb >> 1) & 3;
    const uint32_t bRow = (uint32_t)(rb * 64);

    int r0 = tid >> 2,         u0 = (tid & 3);
    int r1 = (tid + 256) >> 2, u1 = ((tid + 256) & 3);
    int am0 = m0 + r0; if (am0 >= NNODES) am0 = NNODES - 1;
    int am1 = m0 + r1; if (am1 >= NNODES) am1 = NNODES - 1;
    const char* aH0 = (const char*)g_Xh + (size_t)am0 * 640 + u0 * 16;
    const char* aH1 = (const char*)g_Xh + (size_t)am1 * 640 + u1 * 16;
    const char* aL0 = (const char*)g_Xl + (size_t)am0 * 640 + u0 * 16;
    const char* aL1 = (const char*)g_Xl + (size_t)am1 * 640 + u1 * 16;
    const char* bH0 = (const char*)g_Wh + (size_t)r0 * 640 + u0 * 16;
    const char* bH1 = (const char*)g_Wh + (size_t)r1 * 640 + u1 * 16;
    const char* bL0 = (const char*)g_Wl + (size_t)r0 * 640 + u0 * 16;
    const char* bL1 = (const char*)g_Wl + (size_t)r1 * 640 + u1 * 16;
    const uint32_t d0 = (uint32_t)(r0 * 64 + ((u0 ^ ((r0 >> 1) & 3)) * 16));
    const uint32_t d1 = (uint32_t)(r1 * 64 + ((u1 ^ ((r1 >> 1) & 3)) * 16));

    float C[2][8][4];
    #pragma unroll
    for (int a = 0; a < 2; a++)
        #pragma unroll
        for (int j = 0; j < 8; j++)
            #pragma unroll
            for (int q = 0; q < 4; q++) C[a][j][q] = 0.f;

    #pragma unroll
    for (int pc = 0; pc < 2; pc++) {
        uint32_t st = sb + pc * STAGE;
        size_t g = (size_t)pc * 64;
        cpa16(st + d0, aH0 + g);            cpa16(st + d1, aH1 + g);
        cpa16(st + ABYTES + d0, aL0 + g);   cpa16(st + ABYTES + d1, aL1 + g);
        cpa16(st + 2*ABYTES + d0, bH0 + g); cpa16(st + 2*ABYTES + d1, bH1 + g);
        cpa16(st + 3*ABYTES + d0, bL0 + g); cpa16(st + 3*ABYTES + d1, bL1 + g);
        CP_COMMIT();
    }

    int slot = 0, nslot = 2;
    #pragma unroll 1
    for (int ch = 0; ch < 10; ch++) {
        if (ch < 9) { CP_WAIT1(); } else { CP_WAIT0(); }
        __syncthreads();
        if (ch < 8) {
            uint32_t st = sb + nslot * STAGE;
            size_t g = (size_t)(ch + 2) * 64;
            cpa16(st + d0, aH0 + g);            cpa16(st + d1, aH1 + g);
            cpa16(st + ABYTES + d0, aL0 + g);   cpa16(st + ABYTES + d1, aL1 + g);
            cpa16(st + 2*ABYTES + d0, bH0 + g); cpa16(st + 2*ABYTES + d1, bH1 + g);
            cpa16(st + 3*ABYTES + d0, bL0 + g); cpa16(st + 3*ABYTES + d1, bL1 + g);
            CP_COMMIT();
        }

        const uint32_t st  = sb + slot * STAGE;
        const uint32_t sAh = st + aRow;
        const uint32_t sAl = st + ABYTES + aRow;
        const uint32_t sBh = st + 2 * ABYTES + bRow;
        const uint32_t sBl = st + 3 * ABYTES + bRow;

        #pragma unroll
        for (int s = 0; s < 2; s++) {
            const uint32_t ca = (uint32_t)(((2 * s + ahi) ^ swa) << 4);
            const uint32_t cb = (uint32_t)(((2 * s + bhi) ^ swb) << 4);
            uint32_t ah[2][4], al[2][4], bb[16];

            ldsm_x4(ah[0], sAh + ca);
            ldsm_x4(ah[1], sAh + 1024 + ca);
            #pragma unroll
            for (int p = 0; p < 4; p++)
                ldsm_x4(&bb[4 * p], sBh + (uint32_t)(p * 1024) + cb);
            #pragma unroll
            for (int a = 0; a < 2; a++)
                #pragma unroll
                for (int j = 0; j < 8; j++)
                    mma16816(C[a][j], ah[a], &bb[j * 2]);

            ldsm_x4(al[0], sAl + ca);
            ldsm_x4(al[1], sAl + 1024 + ca);
            #pragma unroll
            for (int a = 0; a < 2; a++)
                #pragma unroll
                for (int j = 0; j < 8; j++)
                    mma16816(C[a][j], al[a], &bb[j * 2]);

            #pragma unroll
            for (int p = 0; p < 4; p++)
                ldsm_x4(&bb[4 * p], sBl + (uint32_t)(p * 1024) + cb);
            #pragma unroll
            for (int a = 0; a < 2; a++)
                #pragma unroll
                for (int j = 0; j < 8; j++)
                    mma16816(C[a][j], ah[a], &bb[j * 2]);
        }
        slot  = (slot == 2) ? 0 : slot + 1;
        nslot = (nslot == 2) ? 0 : nslot + 1;
    }

    #pragma unroll
    for (int a = 0; a < 2; a++) {
        int row = m0 + mw + a * 16 + (lane >> 2);
        #pragma unroll
        for (int j = 0; j < 8; j++) {
            int col = nw + j * 8 + 2 * (lane & 3);
            float bx = g_bias[col], by = g_bias[col + 1];
            if (row < NNODES) {
                float2 o;
                o.x = fmaxf(C[a][j][0] + bx, 0.f);
                o.y = fmaxf(C[a][j][1] + by, 0.f);
                *(float2*)(out + (size_t)row * EMB_DIM + col) = o;
            }
            if (row + 8 < NNODES) {
                float2 o;
                o.x = fmaxf(C[a][j][2] + bx, 0.f);
                o.y = fmaxf(C[a][j][3] + by, 0.f);
                *(float2*)(out + (size_t)(row + 8) * EMB_DIM + col) = o;
            }
        }
    }
}

// ===========================================================================
// inputs: node_feat, edge_feat, src_idx, W_edge, b_edge, W_lin, b_lin
// ===========================================================================
extern "C" void kernel_launch(void* const* d_in, const int* in_sizes, int n_in,
                              void* d_out, int out_size) {
    const float* node_feat = (const float*)d_in[0];
    const float* edge_feat = (const float*)d_in[1];
    const int*   src_idx   = (const int*)  d_in[2];
    const float* W_edge    = (const float*)d_in[3];
    const float* b_edge    = (const float*)d_in[4];
    const float* W_lin     = (const float*)d_in[5];
    const float* b_lin     = (const float*)d_in[6];
    float*       out       = (float*)d_out;
    (void)in_sizes; (void)n_in; (void)out_size;

    static int once = 0;
    if (!once) {
        cudaFuncSetAttribute(gemm_mma, cudaFuncAttributeMaxDynamicSharedMemorySize, SM_TOTAL);
        once = 1;
    }

    aggregate_all<<<AGGB + FOLDB, 256>>>(node_feat, edge_feat, src_idx,
                                         W_edge, b_edge, W_lin, b_lin);
    gemm_mma<<<(NNODES + 127) / 128, 256, SM_TOTAL>>>(out);
}

// round 12
// speedup vs baseline: 1.1505x; 1.1505x over previous
#include <cuda_runtime.h>
#include <cuda_bf16.h>
#include <cstdint>

#define NNODES   100000
#define SSAMP    16
#define NODE_DIM 128
#define EDGE_DIM 64
#define EMB_DIM  128
#define KTOT     320            // 128 self + 128 neigh-agg + 64 edge-mean

// ---------------- device-global scratch (no allocs allowed) ------------------
__device__ __align__(16) __nv_bfloat16 g_Xh[(size_t)NNODES * KTOT];
__device__ __align__(16) __nv_bfloat16 g_Xl[(size_t)NNODES * KTOT];
__device__ __align__(16) __nv_bfloat16 g_Wh[EMB_DIM * KTOT];  // folded W^T [n][k], hi
__device__ __align__(16) __nv_bfloat16 g_Wl[EMB_DIM * KTOT];  // lo
__device__ float g_bias[EMB_DIM];

// ---------------- helpers ----------------------------------------------------
__device__ __forceinline__ uint32_t smem_u32(const void* p) {
    uint32_t a;
    asm("{ .reg .u64 t; cvta.to.shared.u64 t, %1; cvt.u32.u64 %0, t; }" : "=r"(a) : "l"(p));
    return a;
}
__device__ __forceinline__ void ldsm_x4(uint32_t* r, uint32_t addr) {
    asm volatile("ldmatrix.sync.aligned.m8n8.x4.shared.b16 {%0,%1,%2,%3}, [%4];"
        : "=r"(r[0]), "=r"(r[1]), "=r"(r[2]), "=r"(r[3]) : "r"(addr));
}
__device__ __forceinline__ void mma16816(float* d, const uint32_t* a, const uint32_t* b) {
    asm volatile("mma.sync.aligned.m16n8k16.row.col.f32.bf16.bf16.f32 "
        "{%0,%1,%2,%3}, {%4,%5,%6,%7}, {%8,%9}, {%0,%1,%2,%3};"
        : "+f"(d[0]), "+f"(d[1]), "+f"(d[2]), "+f"(d[3])
        : "r"(a[0]), "r"(a[1]), "r"(a[2]), "r"(a[3]), "r"(b[0]), "r"(b[1]));
}
__device__ __forceinline__ void cpa16(uint32_t dst, const void* src) {
    asm volatile("cp.async.cg.shared.global [%0], [%1], 16;" :: "r"(dst), "l"(src));
}
#define CP_COMMIT() asm volatile("cp.async.commit_group;" ::: "memory")
#define CP_WAIT1()  asm volatile("cp.async.wait_group 1;" ::: "memory")
#define CP_WAIT0()  asm volatile("cp.async.wait_group 0;" ::: "memory")

__device__ __forceinline__ uint32_t pack_bf2(float x, float y) {
    __nv_bfloat162 h = __floats2bfloat162_rn(x, y);
    return *(uint32_t*)&h;
}
__device__ __forceinline__ void split_store_g(__nv_bfloat16* hp, __nv_bfloat16* lp, float4 v) {
    __nv_bfloat16 hx = __float2bfloat16_rn(v.x);
    __nv_bfloat16 hy = __float2bfloat16_rn(v.y);
    __nv_bfloat16 hz = __float2bfloat16_rn(v.z);
    __nv_bfloat16 hw = __float2bfloat16_rn(v.w);
    __nv_bfloat162 h01 = __halves2bfloat162(hx, hy);
    __nv_bfloat162 h23 = __halves2bfloat162(hz, hw);
    uint32_t l01 = pack_bf2(v.x - __bfloat162float(hx), v.y - __bfloat162float(hy));
    uint32_t l23 = pack_bf2(v.z - __bfloat162float(hz), v.w - __bfloat162float(hw));
    *(uint2*)hp = make_uint2(*(uint32_t*)&h01, *(uint32_t*)&h23);
    *(uint2*)lp = make_uint2(l01, l23);
}
// convert fp32x4 -> (hi uint2, lo uint2)
__device__ __forceinline__ void split4(float4 v, uint2* hv, uint2* lv) {
    __nv_bfloat16 hx = __float2bfloat16_rn(v.x);
    __nv_bfloat16 hy = __float2bfloat16_rn(v.y);
    __nv_bfloat16 hz = __float2bfloat16_rn(v.z);
    __nv_bfloat16 hw = __float2bfloat16_rn(v.w);
    __nv_bfloat162 h01 = __halves2bfloat162(hx, hy);
    __nv_bfloat162 h23 = __halves2bfloat162(hz, hw);
    hv->x = *(uint32_t*)&h01;
    hv->y = *(uint32_t*)&h23;
    lv->x = pack_bf2(v.x - __bfloat162float(hx), v.y - __bfloat162float(hy));
    lv->y = pack_bf2(v.z - __bfloat162float(hz), v.w - __bfloat162float(hw));
}

// ===========================================================================
// K0: self convert -> X cols 0:127, + weight fold
//   8 block-strided coalesced float4 loads per thread (MLP=8, nL=1 each)
// ===========================================================================
#define NTOT  ((size_t)NNODES * NODE_DIM)       // 12.8M floats
#define CONVB 1563                              // ceil(12.8M / 8192)
#define FOLDB 41

__global__ __launch_bounds__(256) void convert_fold(
        const float* __restrict__ node_feat,
        const float* __restrict__ W_edge, const float* __restrict__ b_edge,
        const float* __restrict__ W_lin,  const float* __restrict__ b_lin) {
    const int tid = threadIdx.x;
    if (blockIdx.x < CONVB) {
        size_t base = (size_t)blockIdx.x * 8192 + (size_t)tid * 4;

        float4 v[8];
        #pragma unroll
        for (int i = 0; i < 8; i++) {
            size_t idx = base + (size_t)i * 1024;
            v[i] = (idx < NTOT) ? *(const float4*)(node_feat + idx)
                                : make_float4(0.f, 0.f, 0.f, 0.f);
        }

        #pragma unroll
        for (int i = 0; i < 8; i++) {
            size_t idx = base + (size_t)i * 1024;
            if (idx < NTOT) {
                int row = (int)(idx >> 7), col = (int)(idx & 127);
                uint2 hv, lv;
                split4(v[i], &hv, &lv);
                *(uint2*)(g_Xh + (size_t)row * KTOT + col) = hv;
                *(uint2*)(g_Xl + (size_t)row * KTOT + col) = lv;
            }
        }
        return;
    }
    int kid = blockIdx.x - CONVB;          // 0..40
    if (kid == 40) {
        int j = tid;
        if (j < EMB_DIM) {
            float acc = b_lin[j];
            for (int c = 0; c < NODE_DIM; c++)
                acc += b_edge[c] * W_lin[(NODE_DIM + c) * EMB_DIM + j];
            g_bias[j] = acc;
        }
        return;
    }
    int kk = tid >> 7;
    int j  = tid & 127;
    #pragma unroll
    for (int r = 0; r < 4; r++) {
        int k = kid * 8 + r * 2 + kk;      // 0..319
        float w;
        if (k < 2 * NODE_DIM) {
            w = W_lin[k * EMB_DIM + j];
        } else {
            int e = k - 2 * NODE_DIM;
            float acc = 0.f;
            #pragma unroll 4
            for (int c = 0; c < NODE_DIM; c++)
                acc += W_edge[e * NODE_DIM + c] * W_lin[(NODE_DIM + c) * EMB_DIM + j];
            w = acc;
        }
        __nv_bfloat16 h = __float2bfloat16_rn(w);
        g_Wh[j * KTOT + k] = h;
        g_Wl[j * KTOT + k] = __float2bfloat16_rn(w - __bfloat162float(h));
    }
}

// ===========================================================================
// K1: combined edge-mean (DRAM stream) + gather-mean (L2), warp per node.
// ===========================================================================
__global__ __launch_bounds__(256) void aggregate(
        const float* __restrict__ edge_feat,
        const int*   __restrict__ src_idx) {
    int node = (int)((blockIdx.x * blockDim.x + threadIdx.x) >> 5);
    if (node >= NNODES) return;
    int lane = threadIdx.x & 31;

    // edge mean (lanes split even/odd rows)
    const float* ep = edge_feat + (size_t)node * (SSAMP * EDGE_DIM);
    int halfrow = lane >> 4, cg = lane & 15;
    float4 ea = make_float4(0.f, 0.f, 0.f, 0.f);
    #pragma unroll
    for (int r = 0; r < SSAMP; r += 2) {
        float4 v = *(const float4*)(ep + (size_t)(r + halfrow) * EDGE_DIM + cg * 4);
        ea.x += v.x; ea.y += v.y; ea.z += v.z; ea.w += v.w;
    }

    // neighbor gather mean from bf16-hi rows
    int s = 0;
    if (lane < SSAMP) s = src_idx[(size_t)node * SSAMP + lane];
    float4 na = make_float4(0.f, 0.f, 0.f, 0.f);
    #pragma unroll
    for (int r = 0; r < SSAMP; r++) {
        int sr = __shfl_sync(0xffffffffu, s, r);
        uint2 pv = *(const uint2*)(g_Xh + (size_t)sr * KTOT + lane * 4);
        float2 f0 = __bfloat1622float2(*(const __nv_bfloat162*)&pv.x);
        float2 f1 = __bfloat1622float2(*(const __nv_bfloat162*)&pv.y);
        na.x += f0.x; na.y += f0.y; na.z += f1.x; na.w += f1.y;
    }

    ea.x += __shfl_xor_sync(0xffffffffu, ea.x, 16);
    ea.y += __shfl_xor_sync(0xffffffffu, ea.y, 16);
    ea.z += __shfl_xor_sync(0xffffffffu, ea.z, 16);
    ea.w += __shfl_xor_sync(0xffffffffu, ea.w, 16);

    const float inv = 1.0f / (float)SSAMP;
    na.x *= inv; na.y *= inv; na.z *= inv; na.w *= inv;
    split_store_g(g_Xh + (size_t)node * KTOT + 128 + lane * 4,
                  g_Xl + (size_t)node * KTOT + 128 + lane * 4, na);
    if (lane < 16) {
        ea.x *= inv; ea.y *= inv; ea.z *= inv; ea.w *= inv;
        split_store_g(g_Xh + (size_t)node * KTOT + 256 + cg * 4,
                      g_Xl + (size_t)node * KTOT + 256 + cg * 4, ea);
    }
}

// ===========================================================================
// K2: split-bf16 GEMM, XOR-swizzled 64B smem rows, 3-stage cp.async ring.
//   Inner loop reordered: Al ldsm hoisted beside Ah (independent of products
//   1-2) so its LDS latency hides under the hi-product mma stream.
// ===========================================================================
#define ABYTES   8192                     // 128 rows x 64B
#define STAGE    (4 * ABYTES)             // Ah, Al, Bh, Bl = 32KB
#define NSTAGE   3
#define SM_TOTAL (NSTAGE * STAGE)         // 98304

__global__ __launch_bounds__(256, 2) void gemm_mma(float* __restrict__ out) {
    extern __shared__ unsigned char smem[];
    const int tid  = threadIdx.x;
    const int lane = tid & 31;
    const int wid  = tid >> 5;
    const int m0   = blockIdx.x * 128;

    const int mw = (wid & 3) * 32;
    const int nw = (wid >> 2) * 64;
    const uint32_t sb = smem_u32(smem);

    const int ra  = mw + (lane & 15);
    const int ahi = lane >> 4;
    const int swa = (ra >> 1) & 3;
    const uint32_t aRow = (uint32_t)(ra * 64);

    const int rb  = nw + ((lane >> 4) << 3) + (lane & 7);
    const int bhi = (lane >> 3) & 1;
    const int swb = (rb >> 1) & 3;
    const uint32_t bRow = (uint32_t)(rb * 64);

    int r0 = tid >> 2,         u0 = (tid & 3);
    int r1 = (tid + 256) >> 2, u1 = ((tid + 256) & 3);
    int am0 = m0 + r0; if (am0 >= NNODES) am0 = NNODES - 1;
    int am1 = m0 + r1; if (am1 >= NNODES) am1 = NNODES - 1;
    const char* aH0 = (const char*)g_Xh + (size_t)am0 * 640 + u0 * 16;
    const char* aH1 = (const char*)g_Xh + (size_t)am1 * 640 + u1 * 16;
    const char* aL0 = (const char*)g_Xl + (size_t)am0 * 640 + u0 * 16;
    const char* aL1 = (const char*)g_Xl + (size_t)am1 * 640 + u1 * 16;
    const char* bH0 = (const char*)g_Wh + (size_t)r0 * 640 + u0 * 16;
    const char* bH1 = (const char*)g_Wh + (size_t)r1 * 640 + u1 * 16;
    const char* bL0 = (const char*)g_Wl + (size_t)r0 * 640 + u0 * 16;
    const char* bL1 = (const char*)g_Wl + (size_t)r1 * 640 + u1 * 16;
    const uint32_t d0 = (uint32_t)(r0 * 64 + ((u0 ^ ((r0 >> 1) & 3)) * 16));
    const uint32_t d1 = (uint32_t)(r1 * 64 + ((u1 ^ ((r1 >> 1) & 3)) * 16));

    float C[2][8][4];
    #pragma unroll
    for (int a = 0; a < 2; a++)
        #pragma unroll
        for (int j = 0; j < 8; j++)
            #pragma unroll
            for (int q = 0; q < 4; q++) C[a][j][q] = 0.f;

    #pragma unroll
    for (int pc = 0; pc < 2; pc++) {
        uint32_t st = sb + pc * STAGE;
        size_t g = (size_t)pc * 64;
        cpa16(st + d0, aH0 + g);            cpa16(st + d1, aH1 + g);
        cpa16(st + ABYTES + d0, aL0 + g);   cpa16(st + ABYTES + d1, aL1 + g);
        cpa16(st + 2*ABYTES + d0, bH0 + g); cpa16(st + 2*ABYTES + d1, bH1 + g);
        cpa16(st + 3*ABYTES + d0, bL0 + g); cpa16(st + 3*ABYTES + d1, bL1 + g);
        CP_COMMIT();
    }

    int slot = 0, nslot = 2;
    #pragma unroll 1
    for (int ch = 0; ch < 10; ch++) {
        if (ch < 9) { CP_WAIT1(); } else { CP_WAIT0(); }
        __syncthreads();
        if (ch < 8) {
            uint32_t st = sb + nslot * STAGE;
            size_t g = (size_t)(ch + 2) * 64;
            cpa16(st + d0, aH0 + g);            cpa16(st + d1, aH1 + g);
            cpa16(st + ABYTES + d0, aL0 + g);   cpa16(st + ABYTES + d1, aL1 + g);
            cpa16(st + 2*ABYTES + d0, bH0 + g); cpa16(st + 2*ABYTES + d1, bH1 + g);
            cpa16(st + 3*ABYTES + d0, bL0 + g); cpa16(st + 3*ABYTES + d1, bL1 + g);
            CP_COMMIT();
        }

        const uint32_t st  = sb + slot * STAGE;
        const uint32_t sAh = st + aRow;
        const uint32_t sAl = st + ABYTES + aRow;
        const uint32_t sBh = st + 2 * ABYTES + bRow;
        const uint32_t sBl = st + 3 * ABYTES + bRow;

        #pragma unroll
        for (int s = 0; s < 2; s++) {
            const uint32_t ca = (uint32_t)(((2 * s + ahi) ^ swa) << 4);
            const uint32_t cb = (uint32_t)(((2 * s + bhi) ^ swb) << 4);
            uint32_t ah[2][4], al[2][4], bb[16];

            // issue ALL independent loads up front: Ah, Al, Bh
            ldsm_x4(ah[0], sAh + ca);
            ldsm_x4(ah[1], sAh + 1024 + ca);
            ldsm_x4(al[0], sAl + ca);
            ldsm_x4(al[1], sAl + 1024 + ca);
            #pragma unroll
            for (int p = 0; p < 4; p++)
                ldsm_x4(&bb[4 * p], sBh + (uint32_t)(p * 1024) + cb);

            // P1: Xh @ Wh
            #pragma unroll
            for (int a = 0; a < 2; a++)
                #pragma unroll
                for (int j = 0; j < 8; j++)
                    mma16816(C[a][j], ah[a], &bb[j * 2]);

            // P2: Xl @ Wh (al already in flight / landed)
            #pragma unroll
            for (int a = 0; a < 2; a++)
                #pragma unroll
                for (int j = 0; j < 8; j++)
                    mma16816(C[a][j], al[a], &bb[j * 2]);

            // P3: Xh @ Wl (bb reused after P2 consumed it)
            #pragma unroll
            for (int p = 0; p < 4; p++)
                ldsm_x4(&bb[4 * p], sBl + (uint32_t)(p * 1024) + cb);
            #pragma unroll
            for (int a = 0; a < 2; a++)
                #pragma unroll
                for (int j = 0; j < 8; j++)
                    mma16816(C[a][j], ah[a], &bb[j * 2]);
        }
        slot  = (slot == 2) ? 0 : slot + 1;
        nslot = (nslot == 2) ? 0 : nslot + 1;
    }

    #pragma unroll
    for (int a = 0; a < 2; a++) {
        int row = m0 + mw + a * 16 + (lane >> 2);
        #pragma unroll
        for (int j = 0; j < 8; j++) {
            int col = nw + j * 8 + 2 * (lane & 3);
            float bx = g_bias[col], by = g_bias[col + 1];
            if (row < NNODES) {
                float2 o;
                o.x = fmaxf(C[a][j][0] + bx, 0.f);
                o.y = fmaxf(C[a][j][1] + by, 0.f);
                *(float2*)(out + (size_t)row * EMB_DIM + col) = o;
            }
            if (row + 8 < NNODES) {
                float2 o;
                o.x = fmaxf(C[a][j][2] + bx, 0.f);
                o.y = fmaxf(C[a][j][3] + by, 0.f);
                *(float2*)(out + (size_t)(row + 8) * EMB_DIM + col) = o;
            }
        }
    }
}

// ===========================================================================
// inputs: node_feat, edge_feat, src_idx, W_edge, b_edge, W_lin, b_lin
// ===========================================================================
extern "C" void kernel_launch(void* const* d_in, const int* in_sizes, int n_in,
                              void* d_out, int out_size) {
    const float* node_feat = (const float*)d_in[0];
    const float* edge_feat = (const float*)d_in[1];
    const int*   src_idx   = (const int*)  d_in[2];
    const float* W_edge    = (const float*)d_in[3];
    const float* b_edge    = (const float*)d_in[4];
    const float* W_lin     = (const float*)d_in[5];
    const float* b_lin     = (const float*)d_in[6];
    float*       out       = (float*)d_out;
    (void)in_sizes; (void)n_in; (void)out_size;

    static int once = 0;
    if (!once) {
        cudaFuncSetAttribute(gemm_mma, cudaFuncAttributeMaxDynamicSharedMemorySize, SM_TOTAL);
        once = 1;
    }

    convert_fold<<<CONVB + FOLDB, 256>>>(node_feat, W_edge, b_edge, W_lin, b_lin);
    aggregate<<<12500, 256>>>(edge_feat, src_idx);
    gemm_mma<<<(NNODES + 127) / 128, 256, SM_TOTAL>>>(out);
}

// round 13
// speedup vs baseline: 1.3178x; 1.1454x over previous
#include <cuda_runtime.h>
#include <cuda_bf16.h>
#include <cstdint>

#define NNODES   100000
#define SSAMP    16
#define NODE_DIM 128
#define EDGE_DIM 64
#define EMB_DIM  128
#define KTOT     320            // 128 self + 128 neigh-agg + 64 edge-mean

// ---------------- device-global scratch (no allocs allowed) ------------------
__device__ __align__(16) float         g_Xs[(size_t)NNODES * NODE_DIM]; // tf32-rounded self
__device__ __align__(16) __nv_bfloat16 g_Nh[(size_t)NNODES * NODE_DIM]; // bf16 gather table
__device__ __align__(16) float         g_A [(size_t)NNODES * NODE_DIM]; // tf32 neigh mean
__device__ __align__(16) float         g_Eb[(size_t)NNODES * EDGE_DIM]; // tf32 edge mean
__device__ __align__(16) float         g_Wt[EMB_DIM * KTOT];            // tf32 W^T [n][k]
__device__ float g_bias[EMB_DIM];

// ---------------- helpers ----------------------------------------------------
__device__ __forceinline__ uint32_t smem_u32(const void* p) {
    uint32_t a;
    asm("{ .reg .u64 t; cvta.to.shared.u64 t, %1; cvt.u32.u64 %0, t; }" : "=r"(a) : "l"(p));
    return a;
}
__device__ __forceinline__ float tf32r(float x) {
    uint32_t u;
    asm("cvt.rna.tf32.f32 %0, %1;" : "=r"(u) : "f"(x));
    return __uint_as_float(u);
}
__device__ __forceinline__ void ldsm_x4(uint32_t* r, uint32_t addr) {
    asm volatile("ldmatrix.sync.aligned.m8n8.x4.shared.b16 {%0,%1,%2,%3}, [%4];"
        : "=r"(r[0]), "=r"(r[1]), "=r"(r[2]), "=r"(r[3]) : "r"(addr));
}
__device__ __forceinline__ void mma1688(float* d, const uint32_t* a, const uint32_t* b) {
    asm volatile("mma.sync.aligned.m16n8k8.row.col.f32.tf32.tf32.f32 "
        "{%0,%1,%2,%3}, {%4,%5,%6,%7}, {%8,%9}, {%0,%1,%2,%3};"
        : "+f"(d[0]), "+f"(d[1]), "+f"(d[2]), "+f"(d[3])
        : "r"(a[0]), "r"(a[1]), "r"(a[2]), "r"(a[3]), "r"(b[0]), "r"(b[1]));
}
__device__ __forceinline__ void cpa16(uint32_t dst, const void* src) {
    asm volatile("cp.async.cg.shared.global [%0], [%1], 16;" :: "r"(dst), "l"(src));
}
#define CP_COMMIT() asm volatile("cp.async.commit_group;" ::: "memory")
#define CP_WAIT1()  asm volatile("cp.async.wait_group 1;" ::: "memory")
#define CP_WAIT0()  asm volatile("cp.async.wait_group 0;" ::: "memory")

// ===========================================================================
// K0: self convert (coalesced MLP=8):
//   g_Xs = tf32-rounded node_feat (fp32), g_Nh = bf16 gather table.
//   + weight fold -> g_Wt (tf32-rounded fp32), g_bias.
// ===========================================================================
#define NTOT  ((size_t)NNODES * NODE_DIM)       // 12.8M floats
#define CONVB 1563
#define FOLDB 41

__global__ __launch_bounds__(256) void convert_fold(
        const float* __restrict__ node_feat,
        const float* __restrict__ W_edge, const float* __restrict__ b_edge,
        const float* __restrict__ W_lin,  const float* __restrict__ b_lin) {
    const int tid = threadIdx.x;
    if (blockIdx.x < CONVB) {
        size_t base = (size_t)blockIdx.x * 8192 + (size_t)tid * 4;
        float4 v[8];
        #pragma unroll
        for (int i = 0; i < 8; i++) {
            size_t idx = base + (size_t)i * 1024;
            v[i] = (idx < NTOT) ? *(const float4*)(node_feat + idx)
                                : make_float4(0.f, 0.f, 0.f, 0.f);
        }
        #pragma unroll
        for (int i = 0; i < 8; i++) {
            size_t idx = base + (size_t)i * 1024;
            if (idx < NTOT) {
                float4 w;
                w.x = tf32r(v[i].x); w.y = tf32r(v[i].y);
                w.z = tf32r(v[i].z); w.w = tf32r(v[i].w);
                *(float4*)(g_Xs + idx) = w;
                __nv_bfloat162 h01 = __floats2bfloat162_rn(v[i].x, v[i].y);
                __nv_bfloat162 h23 = __floats2bfloat162_rn(v[i].z, v[i].w);
                *(uint2*)(g_Nh + idx) = make_uint2(*(uint32_t*)&h01, *(uint32_t*)&h23);
            }
        }
        return;
    }
    int kid = blockIdx.x - CONVB;          // 0..40
    if (kid == 40) {
        int j = tid;
        if (j < EMB_DIM) {
            float acc = b_lin[j];
            for (int c = 0; c < NODE_DIM; c++)
                acc += b_edge[c] * W_lin[(NODE_DIM + c) * EMB_DIM + j];
            g_bias[j] = acc;
        }
        return;
    }
    int kk = tid >> 7;
    int j  = tid & 127;
    #pragma unroll
    for (int r = 0; r < 4; r++) {
        int k = kid * 8 + r * 2 + kk;      // 0..319
        float w;
        if (k < 2 * NODE_DIM) {
            w = W_lin[k * EMB_DIM + j];
        } else {
            int e = k - 2 * NODE_DIM;
            float acc = 0.f;
            #pragma unroll 4
            for (int c = 0; c < NODE_DIM; c++)
                acc += W_edge[e * NODE_DIM + c] * W_lin[(NODE_DIM + c) * EMB_DIM + j];
            w = acc;
        }
        g_Wt[j * KTOT + k] = tf32r(w);
    }
}

// ===========================================================================
// K1: combined edge-mean (DRAM) + bf16 gather-mean (L2), warp per node.
//     Outputs tf32-rounded fp32 into g_A / g_Eb.
// ===========================================================================
__global__ __launch_bounds__(256) void aggregate(
        const float* __restrict__ edge_feat,
        const int*   __restrict__ src_idx) {
    int node = (int)((blockIdx.x * blockDim.x + threadIdx.x) >> 5);
    if (node >= NNODES) return;
    int lane = threadIdx.x & 31;

    // edge mean (lanes split even/odd rows)
    const float* ep = edge_feat + (size_t)node * (SSAMP * EDGE_DIM);
    int halfrow = lane >> 4, cg = lane & 15;
    float4 ea = make_float4(0.f, 0.f, 0.f, 0.f);
    #pragma unroll
    for (int r = 0; r < SSAMP; r += 2) {
        float4 v = *(const float4*)(ep + (size_t)(r + halfrow) * EDGE_DIM + cg * 4);
        ea.x += v.x; ea.y += v.y; ea.z += v.z; ea.w += v.w;
    }

    // neighbor gather mean from bf16 table (256B rows)
    int s = 0;
    if (lane < SSAMP) s = src_idx[(size_t)node * SSAMP + lane];
    float4 na = make_float4(0.f, 0.f, 0.f, 0.f);
    #pragma unroll
    for (int r = 0; r < SSAMP; r++) {
        int sr = __shfl_sync(0xffffffffu, s, r);
        uint2 pv = *(const uint2*)(g_Nh + (size_t)sr * NODE_DIM + lane * 4);
        float2 f0 = __bfloat1622float2(*(const __nv_bfloat162*)&pv.x);
        float2 f1 = __bfloat1622float2(*(const __nv_bfloat162*)&pv.y);
        na.x += f0.x; na.y += f0.y; na.z += f1.x; na.w += f1.y;
    }

    ea.x += __shfl_xor_sync(0xffffffffu, ea.x, 16);
    ea.y += __shfl_xor_sync(0xffffffffu, ea.y, 16);
    ea.z += __shfl_xor_sync(0xffffffffu, ea.z, 16);
    ea.w += __shfl_xor_sync(0xffffffffu, ea.w, 16);

    const float inv = 1.0f / (float)SSAMP;
    float4 oa;
    oa.x = tf32r(na.x * inv); oa.y = tf32r(na.y * inv);
    oa.z = tf32r(na.z * inv); oa.w = tf32r(na.w * inv);
    *(float4*)(g_A + (size_t)node * NODE_DIM + lane * 4) = oa;
    if (lane < 16) {
        float4 oe;
        oe.x = tf32r(ea.x * inv); oe.y = tf32r(ea.y * inv);
        oe.z = tf32r(ea.z * inv); oe.w = tf32r(ea.w * inv);
        *(float4*)(g_Eb + (size_t)node * EDGE_DIM + cg * 4) = oe;
    }
}

// ===========================================================================
// K2: single-product tf32 GEMM (m16n8k8), XOR-swizzled 128B smem rows,
//     3-stage cp.async ring. CTA 128x128, warp tile 32x64, chunk = 32 k.
// ===========================================================================
#define TILEB    16384                    // 128 rows x 128B, per A / B
#define STAGE    (2 * TILEB)              // 32KB
#define NSTAGE   3
#define SM_TOTAL (NSTAGE * STAGE)         // 98304

__global__ __launch_bounds__(256, 2) void gemm_tf32(float* __restrict__ out) {
    extern __shared__ unsigned char smem[];
    const int tid  = threadIdx.x;
    const int lane = tid & 31;
    const int wid  = tid >> 5;
    const int m0   = blockIdx.x * 128;

    const int mw = (wid & 3) * 32;
    const int nw = (wid >> 2) * 64;
    const uint32_t sb = smem_u32(smem);

    // staging map: 4 elements (16B each) per thread per array
    int er[4], eu[4], mr[4];
    uint32_t dsto[4];
    #pragma unroll
    for (int p = 0; p < 4; p++) {
        int e = tid + p * 256;
        er[p] = e >> 3;
        eu[p] = e & 7;
        int m = m0 + er[p]; if (m >= NNODES) m = NNODES - 1;
        mr[p] = m;
        dsto[p] = (uint32_t)(er[p] * 128 + ((eu[p] ^ (er[p] & 7)) << 4));
    }

    // ldsm lane geometry
    const int row_a = mw + (lane & 7) + (lane & 8);   // +16 rows = +2048B, same key
    const int keyA  = row_a & 7;
    const int selA  = lane >> 4;                       // k-half select
    const int row_b = nw + (lane & 7) + ((lane >> 4) << 3);
    const int keyB  = row_b & 7;
    const int selB  = (lane >> 3) & 1;

    float C[2][8][4];
    #pragma unroll
    for (int a = 0; a < 2; a++)
        #pragma unroll
        for (int j = 0; j < 8; j++)
            #pragma unroll
            for (int q = 0; q < 4; q++) C[a][j][q] = 0.f;

    // ---- stage one chunk: 4 A + 4 B cp.async ----
    auto stage_chunk = [&](int ch, uint32_t st) {
        const char* as; size_t astr;
        if (ch < 4)      { as = (const char*)g_Xs + ch * 128;       astr = 512; }
        else if (ch < 8) { as = (const char*)g_A  + (ch - 4) * 128; astr = 512; }
        else             { as = (const char*)g_Eb + (ch - 8) * 128; astr = 256; }
        const char* bs = (const char*)g_Wt + ch * 128;
        #pragma unroll
        for (int p = 0; p < 4; p++)
            cpa16(st + dsto[p], as + (size_t)mr[p] * astr + eu[p] * 16);
        #pragma unroll
        for (int p = 0; p < 4; p++)
            cpa16(st + TILEB + dsto[p], bs + (size_t)er[p] * 1280 + eu[p] * 16);
        CP_COMMIT();
    };

    stage_chunk(0, sb);
    stage_chunk(1, sb + STAGE);

    int slot = 0, nslot = 2;
    #pragma unroll 1
    for (int ch = 0; ch < 10; ch++) {
        if (ch < 9) { CP_WAIT1(); } else { CP_WAIT0(); }
        __syncthreads();
        if (ch < 8) stage_chunk(ch + 2, sb + nslot * STAGE);

        const uint32_t aBase = sb + slot * STAGE + (uint32_t)(row_a * 128);
        const uint32_t bBase = sb + slot * STAGE + TILEB + (uint32_t)(row_b * 128);

        #pragma unroll
        for (int k = 0; k < 4; k++) {
            const uint32_t ua = (uint32_t)(((2 * k + selA) ^ keyA) << 4);
            const uint32_t ub = (uint32_t)(((2 * k + selB) ^ keyB) << 4);
            uint32_t a[2][4], bb[16];

            ldsm_x4(a[0], aBase + ua);
            ldsm_x4(a[1], aBase + 2048 + ua);
            ldsm_x4(&bb[0],  bBase + ub);
            ldsm_x4(&bb[4],  bBase + 2048 + ub);
            ldsm_x4(&bb[8],  bBase + 4096 + ub);
            ldsm_x4(&bb[12], bBase + 6144 + ub);

            #pragma unroll
            for (int mh = 0; mh < 2; mh++)
                #pragma unroll
                for (int j = 0; j < 8; j++)
                    mma1688(C[mh][j], a[mh], &bb[j * 2]);
        }
        slot  = (slot == 2) ? 0 : slot + 1;
        nslot = (nslot == 2) ? 0 : nslot + 1;
    }

    // epilogue: bias + relu -> out
    #pragma unroll
    for (int a = 0; a < 2; a++) {
        int row = m0 + mw + a * 16 + (lane >> 2);
        #pragma unroll
        for (int j = 0; j < 8; j++) {
            int col = nw + j * 8 + 2 * (lane & 3);
            float bx = g_bias[col], by = g_bias[col + 1];
            if (row < NNODES) {
                float2 o;
                o.x = fmaxf(C[a][j][0] + bx, 0.f);
                o.y = fmaxf(C[a][j][1] + by, 0.f);
                *(float2*)(out + (size_t)row * EMB_DIM + col) = o;
            }
            if (row + 8 < NNODES) {
                float2 o;
                o.x = fmaxf(C[a][j][2] + bx, 0.f);
                o.y = fmaxf(C[a][j][3] + by, 0.f);
                *(float2*)(out + (size_t)(row + 8) * EMB_DIM + col) = o;
            }
        }
    }
}

// ===========================================================================
// inputs: node_feat, edge_feat, src_idx, W_edge, b_edge, W_lin, b_lin
// ===========================================================================
extern "C" void kernel_launch(void* const* d_in, const int* in_sizes, int n_in,
                              void* d_out, int out_size) {
    const float* node_feat = (const float*)d_in[0];
    const float* edge_feat = (const float*)d_in[1];
    const int*   src_idx   = (const int*)  d_in[2];
    const float* W_edge    = (const float*)d_in[3];
    const float* b_edge    = (const float*)d_in[4];
    const float* W_lin     = (const float*)d_in[5];
    const float* b_lin     = (const float*)d_in[6];
    float*       out       = (float*)d_out;
    (void)in_sizes; (void)n_in; (void)out_size;

    static int once = 0;
    if (!once) {
        cudaFuncSetAttribute(gemm_tf32, cudaFuncAttributeMaxDynamicSharedMemorySize, SM_TOTAL);
        once = 1;
    }

    convert_fold<<<CONVB + FOLDB, 256>>>(node_feat, W_edge, b_edge, W_lin, b_lin);
    aggregate<<<12500, 256>>>(edge_feat, src_idx);
    gemm_tf32<<<(NNODES + 127) / 128, 256, SM_TOTAL>>>(out);
}

// round 14
// speedup vs baseline: 1.3671x; 1.0374x over previous
#include <cuda_runtime.h>
#include <cuda_bf16.h>
#include <cstdint>

#define NNODES   100000
#define SSAMP    16
#define NODE_DIM 128
#define EDGE_DIM 64
#define EMB_DIM  128
#define KTOT     320            // 128 self + 128 neigh-agg + 64 edge-mean

// ---------------- device-global scratch (no allocs allowed) ------------------
__device__ __align__(16) __nv_bfloat16 g_Nh[(size_t)NNODES * NODE_DIM]; // bf16 gather table
__device__ __align__(16) float         g_A [(size_t)NNODES * NODE_DIM]; // tf32 neigh mean
__device__ __align__(16) float         g_Eb[(size_t)NNODES * EDGE_DIM]; // tf32 edge mean
__device__ __align__(16) float         g_Wt[EMB_DIM * KTOT];            // tf32 W^T [n][k]
__device__ float g_bias[EMB_DIM];

// ---------------- helpers ----------------------------------------------------
__device__ __forceinline__ uint32_t smem_u32(const void* p) {
    uint32_t a;
    asm("{ .reg .u64 t; cvta.to.shared.u64 t, %1; cvt.u32.u64 %0, t; }" : "=r"(a) : "l"(p));
    return a;
}
__device__ __forceinline__ float tf32r(float x) {
    uint32_t u;
    asm("cvt.rna.tf32.f32 %0, %1;" : "=r"(u) : "f"(x));
    return __uint_as_float(u);
}
__device__ __forceinline__ void ldsm_x4(uint32_t* r, uint32_t addr) {
    asm volatile("ldmatrix.sync.aligned.m8n8.x4.shared.b16 {%0,%1,%2,%3}, [%4];"
        : "=r"(r[0]), "=r"(r[1]), "=r"(r[2]), "=r"(r[3]) : "r"(addr));
}
__device__ __forceinline__ void mma1688(float* d, const uint32_t* a, const uint32_t* b) {
    asm volatile("mma.sync.aligned.m16n8k8.row.col.f32.tf32.tf32.f32 "
        "{%0,%1,%2,%3}, {%4,%5,%6,%7}, {%8,%9}, {%0,%1,%2,%3};"
        : "+f"(d[0]), "+f"(d[1]), "+f"(d[2]), "+f"(d[3])
        : "r"(a[0]), "r"(a[1]), "r"(a[2]), "r"(a[3]), "r"(b[0]), "r"(b[1]));
}
__device__ __forceinline__ void cpa16(uint32_t dst, const void* src) {
    asm volatile("cp.async.cg.shared.global [%0], [%1], 16;" :: "r"(dst), "l"(src));
}
#define CP_COMMIT() asm volatile("cp.async.commit_group;" ::: "memory")
#define CP_WAIT1()  asm volatile("cp.async.wait_group 1;" ::: "memory")
#define CP_WAIT0()  asm volatile("cp.async.wait_group 0;" ::: "memory")

// ===========================================================================
// K0: build bf16 gather table g_Nh (coalesced MLP=8) + weight fold -> g_Wt.
//   (self fp32 columns are staged by the GEMM directly from node_feat;
//    tf32 mma truncates the mantissa in HW, no pre-round copy needed)
// ===========================================================================
#define NTOT  ((size_t)NNODES * NODE_DIM)       // 12.8M floats
#define CONVB 1563
#define FOLDB 41

__global__ __launch_bounds__(256) void convert_fold(
        const float* __restrict__ node_feat,
        const float* __restrict__ W_edge, const float* __restrict__ b_edge,
        const float* __restrict__ W_lin,  const float* __restrict__ b_lin) {
    const int tid = threadIdx.x;
    if (blockIdx.x < CONVB) {
        size_t base = (size_t)blockIdx.x * 8192 + (size_t)tid * 4;
        float4 v[8];
        #pragma unroll
        for (int i = 0; i < 8; i++) {
            size_t idx = base + (size_t)i * 1024;
            v[i] = (idx < NTOT) ? *(const float4*)(node_feat + idx)
                                : make_float4(0.f, 0.f, 0.f, 0.f);
        }
        #pragma unroll
        for (int i = 0; i < 8; i++) {
            size_t idx = base + (size_t)i * 1024;
            if (idx < NTOT) {
                __nv_bfloat162 h01 = __floats2bfloat162_rn(v[i].x, v[i].y);
                __nv_bfloat162 h23 = __floats2bfloat162_rn(v[i].z, v[i].w);
                *(uint2*)(g_Nh + idx) = make_uint2(*(uint32_t*)&h01, *(uint32_t*)&h23);
            }
        }
        return;
    }
    int kid = blockIdx.x - CONVB;          // 0..40
    if (kid == 40) {
        int j = tid;
        if (j < EMB_DIM) {
            float acc = b_lin[j];
            for (int c = 0; c < NODE_DIM; c++)
                acc += b_edge[c] * W_lin[(NODE_DIM + c) * EMB_DIM + j];
            g_bias[j] = acc;
        }
        return;
    }
    int kk = tid >> 7;
    int j  = tid & 127;
    #pragma unroll
    for (int r = 0; r < 4; r++) {
        int k = kid * 8 + r * 2 + kk;      // 0..319
        float w;
        if (k < 2 * NODE_DIM) {
            w = W_lin[k * EMB_DIM + j];
        } else {
            int e = k - 2 * NODE_DIM;
            float acc = 0.f;
            #pragma unroll 4
            for (int c = 0; c < NODE_DIM; c++)
                acc += W_edge[e * NODE_DIM + c] * W_lin[(NODE_DIM + c) * EMB_DIM + j];
            w = acc;
        }
        g_Wt[j * KTOT + k] = tf32r(w);
    }
}

// ===========================================================================
// K1: combined edge-mean (DRAM) + bf16 gather-mean (L2), warp per node.
//     Outputs tf32-rounded fp32 into g_A / g_Eb.
// ===========================================================================
__global__ __launch_bounds__(256) void aggregate(
        const float* __restrict__ edge_feat,
        const int*   __restrict__ src_idx) {
    int node = (int)((blockIdx.x * blockDim.x + threadIdx.x) >> 5);
    if (node >= NNODES) return;
    int lane = threadIdx.x & 31;

    // edge mean (lanes split even/odd rows)
    const float* ep = edge_feat + (size_t)node * (SSAMP * EDGE_DIM);
    int halfrow = lane >> 4, cg = lane & 15;
    float4 ea = make_float4(0.f, 0.f, 0.f, 0.f);
    #pragma unroll
    for (int r = 0; r < SSAMP; r += 2) {
        float4 v = *(const float4*)(ep + (size_t)(r + halfrow) * EDGE_DIM + cg * 4);
        ea.x += v.x; ea.y += v.y; ea.z += v.z; ea.w += v.w;
    }

    // neighbor gather mean from bf16 table (256B rows)
    int s = 0;
    if (lane < SSAMP) s = src_idx[(size_t)node * SSAMP + lane];
    float4 na = make_float4(0.f, 0.f, 0.f, 0.f);
    #pragma unroll
    for (int r = 0; r < SSAMP; r++) {
        int sr = __shfl_sync(0xffffffffu, s, r);
        uint2 pv = *(const uint2*)(g_Nh + (size_t)sr * NODE_DIM + lane * 4);
        float2 f0 = __bfloat1622float2(*(const __nv_bfloat162*)&pv.x);
        float2 f1 = __bfloat1622float2(*(const __nv_bfloat162*)&pv.y);
        na.x += f0.x; na.y += f0.y; na.z += f1.x; na.w += f1.y;
    }

    ea.x += __shfl_xor_sync(0xffffffffu, ea.x, 16);
    ea.y += __shfl_xor_sync(0xffffffffu, ea.y, 16);
    ea.z += __shfl_xor_sync(0xffffffffu, ea.z, 16);
    ea.w += __shfl_xor_sync(0xffffffffu, ea.w, 16);

    const float inv = 1.0f / (float)SSAMP;
    float4 oa;
    oa.x = tf32r(na.x * inv); oa.y = tf32r(na.y * inv);
    oa.z = tf32r(na.z * inv); oa.w = tf32r(na.w * inv);
    *(float4*)(g_A + (size_t)node * NODE_DIM + lane * 4) = oa;
    if (lane < 16) {
        float4 oe;
        oe.x = tf32r(ea.x * inv); oe.y = tf32r(ea.y * inv);
        oe.z = tf32r(ea.z * inv); oe.w = tf32r(ea.w * inv);
        *(float4*)(g_Eb + (size_t)node * EDGE_DIM + cg * 4) = oe;
    }
}

// ===========================================================================
// K2: single-product tf32 GEMM (m16n8k8), XOR-swizzled 128B smem rows,
//     3-stage cp.async ring. Self columns staged straight from node_feat.
// ===========================================================================
#define TILEB    16384                    // 128 rows x 128B, per A / B
#define STAGE    (2 * TILEB)              // 32KB
#define NSTAGE   3
#define SM_TOTAL (NSTAGE * STAGE)         // 98304

__global__ __launch_bounds__(256, 2) void gemm_tf32(const float* __restrict__ node_feat,
                                                    float* __restrict__ out) {
    extern __shared__ unsigned char smem[];
    const int tid  = threadIdx.x;
    const int lane = tid & 31;
    const int wid  = tid >> 5;
    const int m0   = blockIdx.x * 128;

    const int mw = (wid & 3) * 32;
    const int nw = (wid >> 2) * 64;
    const uint32_t sb = smem_u32(smem);

    // staging map: 4 elements (16B each) per thread per array
    int er[4], eu[4], mr[4];
    uint32_t dsto[4];
    #pragma unroll
    for (int p = 0; p < 4; p++) {
        int e = tid + p * 256;
        er[p] = e >> 3;
        eu[p] = e & 7;
        int m = m0 + er[p]; if (m >= NNODES) m = NNODES - 1;
        mr[p] = m;
        dsto[p] = (uint32_t)(er[p] * 128 + ((eu[p] ^ (er[p] & 7)) << 4));
    }

    // ldsm lane geometry
    const int row_a = mw + (lane & 7) + (lane & 8);
    const int keyA  = row_a & 7;
    const int selA  = lane >> 4;
    const int row_b = nw + (lane & 7) + ((lane >> 4) << 3);
    const int keyB  = row_b & 7;
    const int selB  = (lane >> 3) & 1;

    float C[2][8][4];
    #pragma unroll
    for (int a = 0; a < 2; a++)
        #pragma unroll
        for (int j = 0; j < 8; j++)
            #pragma unroll
            for (int q = 0; q < 4; q++) C[a][j][q] = 0.f;

    // ---- stage one chunk: 4 A + 4 B cp.async ----
    auto stage_chunk = [&](int ch, uint32_t st) {
        const char* as; size_t astr;
        if (ch < 4)      { as = (const char*)node_feat + ch * 128;  astr = 512; }
        else if (ch < 8) { as = (const char*)g_A  + (ch - 4) * 128; astr = 512; }
        else             { as = (const char*)g_Eb + (ch - 8) * 128; astr = 256; }
        const char* bs = (const char*)g_Wt + ch * 128;
        #pragma unroll
        for (int p = 0; p < 4; p++)
            cpa16(st + dsto[p], as + (size_t)mr[p] * astr + eu[p] * 16);
        #pragma unroll
        for (int p = 0; p < 4; p++)
            cpa16(st + TILEB + dsto[p], bs + (size_t)er[p] * 1280 + eu[p] * 16);
        CP_COMMIT();
    };

    stage_chunk(0, sb);
    stage_chunk(1, sb + STAGE);

    int slot = 0, nslot = 2;
    #pragma unroll 1
    for (int ch = 0; ch < 10; ch++) {
        if (ch < 9) { CP_WAIT1(); } else { CP_WAIT0(); }
        __syncthreads();
        if (ch < 8) stage_chunk(ch + 2, sb + nslot * STAGE);

        const uint32_t aBase = sb + slot * STAGE + (uint32_t)(row_a * 128);
        const uint32_t bBase = sb + slot * STAGE + TILEB + (uint32_t)(row_b * 128);

        #pragma unroll
        for (int k = 0; k < 4; k++) {
            const uint32_t ua = (uint32_t)(((2 * k + selA) ^ keyA) << 4);
            const uint32_t ub = (uint32_t)(((2 * k + selB) ^ keyB) << 4);
            uint32_t a[2][4], bb[16];

            ldsm_x4(a[0], aBase + ua);
            ldsm_x4(a[1], aBase + 2048 + ua);
            ldsm_x4(&bb[0],  bBase + ub);
            ldsm_x4(&bb[4],  bBase + 2048 + ub);
            ldsm_x4(&bb[8],  bBase + 4096 + ub);
            ldsm_x4(&bb[12], bBase + 6144 + ub);

            #pragma unroll
            for (int mh = 0; mh < 2; mh++)
                #pragma unroll
                for (int j = 0; j < 8; j++)
                    mma1688(C[mh][j], a[mh], &bb[j * 2]);
        }
        slot  = (slot == 2) ? 0 : slot + 1;
        nslot = (nslot == 2) ? 0 : nslot + 1;
    }

    // epilogue: bias + relu -> out
    #pragma unroll
    for (int a = 0; a < 2; a++) {
        int row = m0 + mw + a * 16 + (lane >> 2);
        #pragma unroll
        for (int j = 0; j < 8; j++) {
            int col = nw + j * 8 + 2 * (lane & 3);
            float bx = g_bias[col], by = g_bias[col + 1];
            if (row < NNODES) {
                float2 o;
                o.x = fmaxf(C[a][j][0] + bx, 0.f);
                o.y = fmaxf(C[a][j][1] + by, 0.f);
                *(float2*)(out + (size_t)row * EMB_DIM + col) = o;
            }
            if (row + 8 < NNODES) {
                float2 o;
                o.x = fmaxf(C[a][j][2] + bx, 0.f);
                o.y = fmaxf(C[a][j][3] + by, 0.f);
                *(float2*)(out + (size_t)(row + 8) * EMB_DIM + col) = o;
            }
        }
    }
}

// ===========================================================================
// inputs: node_feat, edge_feat, src_idx, W_edge, b_edge, W_lin, b_lin
// ===========================================================================
extern "C" void kernel_launch(void* const* d_in, const int* in_sizes, int n_in,
                              void* d_out, int out_size) {
    const float* node_feat = (const float*)d_in[0];
    const float* edge_feat = (const float*)d_in[1];
    const int*   src_idx   = (const int*)  d_in[2];
    const float* W_edge    = (const float*)d_in[3];
    const float* b_edge    = (const float*)d_in[4];
    const float* W_lin     = (const float*)d_in[5];
    const float* b_lin     = (const float*)d_in[6];
    float*       out       = (float*)d_out;
    (void)in_sizes; (void)n_in; (void)out_size;

    static int once = 0;
    if (!once) {
        cudaFuncSetAttribute(gemm_tf32, cudaFuncAttributeMaxDynamicSharedMemorySize, SM_TOTAL);
        once = 1;
    }

    convert_fold<<<CONVB + FOLDB, 256>>>(node_feat, W_edge, b_edge, W_lin, b_lin);
    aggregate<<<12500, 256>>>(edge_feat, src_idx);
    gemm_tf32<<<(NNODES + 127) / 128, 256, SM_TOTAL>>>(node_feat, out);
}